// round 16
// baseline (speedup 1.0000x reference)
#include <cuda_runtime.h>

// Problem constants (fixed shapes)
#define T_TOK 8192
#define D_IN  1024
#define H1    128
#define QDIM  32
#define HALFD 8
#define KNN   8
#define NKEYS 256

// k1 tiling: 64 tokens x 128 outputs per block, BK=16, 256 threads.
#define BM 64
#define BN 128
#define BK 16
#define NKT (D_IN / BK)   // 64

// smem strides (floats), padded for bank-conflict-free access, 16B-aligned
#define XS_STRIDE 68      // Xs[k][tok]
#define WS_STRIDE 132     // Ws[k][col]
#define HS_STRIDE 136     // hs[tok][col] (epilogue)

#define XS_BUF (BK * XS_STRIDE)          // 1088 floats
#define WS_BUF (BK * WS_STRIDE)          // 2112 floats
#define SMEM_MAIN  ((2 * XS_BUF + 2 * WS_BUF) * 4)          // 25600 B
#define SMEM_EPI   ((BM * HS_STRIDE + QDIM * H1) * 4)       // 51200 B
#define SMEM_BYTES (SMEM_EPI > SMEM_MAIN ? SMEM_EPI : SMEM_MAIN)

// Scratch (device globals: allocation-free rule)
__device__ __align__(16) float g_q[T_TOK * QDIM];   // 1 MB
__device__ float g_wt[T_TOK * 16];                  // 512 KB
__device__ int   g_id[T_TOK * 16];                  // 512 KB

// Packed dual-fp32 FMA (B300 FFMA2, rt~2 confirmed by R12 ncu)
#define FMA2(d, a, b) asm("fma.rn.f32x2 %0, %1, %2, %0;" : "+l"(d) : "l"(a), "l"(b))
// Duplicate scalar into both halves of a packed operand (alu pipe MOVs)
#define DUP2(d, s)    asm("mov.b64 %0, {%1, %1};" : "=l"(d) : "f"(s))

// ---------------------------------------------------------------------------
// Kernel 1 (fused k1+k2): h = relu(x@W1^T + b1); q = h@W2^T + b2 -> g_q
//   256 threads (8 warps, 2 warp-rows x 4 warp-cols), grid 128.
//   Warp tile 32tok x 32col; lane (tr=lane>>2, cg=lane&3): 4 tok x 8 col.
//   Per k per lane: 1 broadcast LDS.128 (a, 1 wf) + 2 broadcast LDS.128
//   (b col-pairs, 1 wf each) + 8 MOV (a-dup, alu) + 16 FMA2 (fma).
//   L1 ~680 wf/kt/SM vs fma 1024 cyc/SMSP/kt -> fma-bound.
//   Epilogue computes q in-SM (h tile never goes to gmem).
// ---------------------------------------------------------------------------
extern __shared__ __align__(16) char smem_raw[];

__global__ __launch_bounds__(256, 1)
void k1_gemm_relu_q(const float* __restrict__ x, const float* __restrict__ W1,
                    const float* __restrict__ b1, const float* __restrict__ W2,
                    const float* __restrict__ b2)
{
    float* Xs = (float*)smem_raw;                       // [2][BK][XS_STRIDE]
    float* Ws = (float*)(smem_raw + 2 * XS_BUF * 4);    // [2][BK][WS_STRIDE]

    const int tid  = threadIdx.x;
    const int lane = tid & 31;
    const int w    = tid >> 5;
    const int wr   = w >> 2;          // warp row (tokens): 0..1
    const int wc   = w & 3;           // warp col (outputs): 0..3
    const int tr   = lane >> 2;       // lane token group: 0..7
    const int cg   = lane & 3;        // lane col group:   0..3
    const int t0   = blockIdx.x * BM;

    const int tokb = (wr << 5) + (tr << 2);   // lane's 4 tokens
    const int colb = (wc << 5) + (cg << 3);   // lane's 8 cols

    // Loader mapping (line-friendly: 8 lines per warp-LDG)
    const int xt  = tid >> 2;          // X token 0..63
    const int xkq = (tid & 3) << 2;    // X k-quad offset
    const int wcA = tid >> 2;          // W col 0..63 (and +64)
    const int wkq = (tid & 3) << 2;    // W k-quad offset

    const float* xp  = x  + (size_t)(t0 + xt) * D_IN + xkq;
    const float* wpA = W1 + (size_t)wcA * D_IN + wkq;
    const float* wpB = W1 + (size_t)(wcA + 64) * D_IN + wkq;

    unsigned long long acc[4][4];   // [token][col-pair]
#pragma unroll
    for (int t = 0; t < 4; t++)
#pragma unroll
        for (int c = 0; c < 4; c++) acc[t][c] = 0ull;

    float4 pX, pWA, pWB;
    pX  = *(const float4*)(xp);
    pWA = *(const float4*)(wpA);
    pWB = *(const float4*)(wpB);

#define STORE_TILE(buf)                                                        \
    do {                                                                       \
        float* xb = Xs + (buf) * XS_BUF;                                       \
        float* wb = Ws + (buf) * WS_BUF;                                       \
        xb[(xkq + 0) * XS_STRIDE + xt] = pX.x;                                 \
        xb[(xkq + 1) * XS_STRIDE + xt] = pX.y;                                 \
        xb[(xkq + 2) * XS_STRIDE + xt] = pX.z;                                 \
        xb[(xkq + 3) * XS_STRIDE + xt] = pX.w;                                 \
        wb[(wkq + 0) * WS_STRIDE + wcA]      = pWA.x;                          \
        wb[(wkq + 1) * WS_STRIDE + wcA]      = pWA.y;                          \
        wb[(wkq + 2) * WS_STRIDE + wcA]      = pWA.z;                          \
        wb[(wkq + 3) * WS_STRIDE + wcA]      = pWA.w;                          \
        wb[(wkq + 0) * WS_STRIDE + wcA + 64] = pWB.x;                          \
        wb[(wkq + 1) * WS_STRIDE + wcA + 64] = pWB.y;                          \
        wb[(wkq + 2) * WS_STRIDE + wcA + 64] = pWB.z;                          \
        wb[(wkq + 3) * WS_STRIDE + wcA + 64] = pWB.w;                          \
    } while (0)

    STORE_TILE(0);
    __syncthreads();

#pragma unroll 1
    for (int kt = 0; kt < NKT; kt++) {
        const int cur = kt & 1;
        if (kt < NKT - 1) {
            const int k0 = (kt + 1) * BK;
            pX  = *(const float4*)(xp + k0);
            pWA = *(const float4*)(wpA + k0);
            pWB = *(const float4*)(wpB + k0);
        }
        const float* xb = Xs + cur * XS_BUF;
        const float* wb = Ws + cur * WS_BUF;
#pragma unroll
        for (int k = 0; k < BK; k++) {
            // a: 4 tokens, one broadcast LDS.128 (8 uniq addrs / warp)
            const float4 a4 = *(const float4*)&xb[k * XS_STRIDE + tokb];
            unsigned long long ad0, ad1, ad2, ad3;
            DUP2(ad0, a4.x); DUP2(ad1, a4.y); DUP2(ad2, a4.z); DUP2(ad3, a4.w);
            // b: 4 natural col-pairs, two broadcast LDS.128 (4 uniq addrs)
            const ulonglong2 b01 = *(const ulonglong2*)&wb[k * WS_STRIDE + colb];
            const ulonglong2 b23 = *(const ulonglong2*)&wb[k * WS_STRIDE + colb + 4];
            FMA2(acc[0][0], ad0, b01.x); FMA2(acc[0][1], ad0, b01.y);
            FMA2(acc[0][2], ad0, b23.x); FMA2(acc[0][3], ad0, b23.y);
            FMA2(acc[1][0], ad1, b01.x); FMA2(acc[1][1], ad1, b01.y);
            FMA2(acc[1][2], ad1, b23.x); FMA2(acc[1][3], ad1, b23.y);
            FMA2(acc[2][0], ad2, b01.x); FMA2(acc[2][1], ad2, b01.y);
            FMA2(acc[2][2], ad2, b23.x); FMA2(acc[2][3], ad2, b23.y);
            FMA2(acc[3][0], ad3, b01.x); FMA2(acc[3][1], ad3, b01.y);
            FMA2(acc[3][2], ad3, b23.x); FMA2(acc[3][3], ad3, b23.y);
        }
        if (kt < NKT - 1) STORE_TILE(cur ^ 1);
        __syncthreads();
    }

    // ---------------- Epilogue: bias+relu -> hs (smem), then q ----------------
    float* hs  = (float*)smem_raw;                               // [64][HS_STRIDE]
    float* W2s = (float*)(smem_raw + BM * HS_STRIDE * 4);        // [128][32] = W2^T

    const float4 bA = __ldg((const float4*)(b1 + colb));
    const float4 bB = __ldg((const float4*)(b1 + colb + 4));
#pragma unroll
    for (int t = 0; t < 4; t++) {
        float4 lo, hi;
        lo.x = __uint_as_float((unsigned)(acc[t][0]))       + bA.x;
        lo.y = __uint_as_float((unsigned)(acc[t][0] >> 32)) + bA.y;
        lo.z = __uint_as_float((unsigned)(acc[t][1]))       + bA.z;
        lo.w = __uint_as_float((unsigned)(acc[t][1] >> 32)) + bA.w;
        hi.x = __uint_as_float((unsigned)(acc[t][2]))       + bB.x;
        hi.y = __uint_as_float((unsigned)(acc[t][2] >> 32)) + bB.y;
        hi.z = __uint_as_float((unsigned)(acc[t][3]))       + bB.z;
        hi.w = __uint_as_float((unsigned)(acc[t][3] >> 32)) + bB.w;
        lo.x = fmaxf(lo.x, 0.f); lo.y = fmaxf(lo.y, 0.f);
        lo.z = fmaxf(lo.z, 0.f); lo.w = fmaxf(lo.w, 0.f);
        hi.x = fmaxf(hi.x, 0.f); hi.y = fmaxf(hi.y, 0.f);
        hi.z = fmaxf(hi.z, 0.f); hi.w = fmaxf(hi.w, 0.f);
        *(float4*)&hs[(tokb + t) * HS_STRIDE + colb]     = lo;
        *(float4*)&hs[(tokb + t) * HS_STRIDE + colb + 4] = hi;
    }

    // W2^T into smem: W2 is [c][j] (32 x 128); store W2s[j*32 + c]
#pragma unroll
    for (int idx = tid; idx < QDIM * H1; idx += 256) {
        const int c = idx >> 7, j = idx & 127;
        W2s[j * QDIM + c] = W2[idx];
    }
    __syncthreads();

    // q: thread -> token tid>>2, q-dims (tid&3)*8..+7. j-order matches old k2
    {
        const int tok = tid >> 2;
        const int qg  = (tid & 3) << 3;
        float4 qa = __ldg((const float4*)(b2 + qg));
        float4 qb = __ldg((const float4*)(b2 + qg + 4));
#pragma unroll 8
        for (int j = 0; j < H1; j += 4) {
            const float4 h4 = *(const float4*)&hs[tok * HS_STRIDE + j];
#pragma unroll
            for (int jj = 0; jj < 4; jj++) {
                const float hv = (jj == 0) ? h4.x : (jj == 1) ? h4.y
                               : (jj == 2) ? h4.z : h4.w;
                const float4 wA = *(const float4*)&W2s[(j + jj) * QDIM + qg];
                const float4 wB = *(const float4*)&W2s[(j + jj) * QDIM + qg + 4];
                qa.x = fmaf(hv, wA.x, qa.x); qa.y = fmaf(hv, wA.y, qa.y);
                qa.z = fmaf(hv, wA.z, qa.z); qa.w = fmaf(hv, wA.w, qa.w);
                qb.x = fmaf(hv, wB.x, qb.x); qb.y = fmaf(hv, wB.y, qb.y);
                qb.z = fmaf(hv, wB.z, qb.z); qb.w = fmaf(hv, wB.w, qb.w);
            }
        }
        *(float4*)&g_q[(size_t)(t0 + tok) * QDIM + qg]     = qa;
        *(float4*)&g_q[(size_t)(t0 + tok) * QDIM + qg + 4] = qb;
    }
}

// ---------------------------------------------------------------------------
// Kernel 3: scores + top-k + combine + softmax (R9-proven version)
// Tie-breaking matches lax.top_k (lowest index first).
// ---------------------------------------------------------------------------
__global__ __launch_bounds__(256, 1)
void k3_topk(const float* __restrict__ keys)
{
    __shared__ float ks[2 * 2 * NKEYS * HALFD];   // 32 KB
    __shared__ float sc_s[8][2][2][KNN];
    __shared__ int   id_s[8][2][2][KNN];
    __shared__ float fsc_s[8][2][KNN];
    __shared__ int   fid_s[8][2][KNN];

    const int tid = threadIdx.x;
    for (int i = tid; i < 2 * 2 * NKEYS * HALFD; i += 256) ks[i] = keys[i];
    __syncthreads();

    const int w    = tid >> 5;
    const int lane = tid & 31;
    const int t    = blockIdx.x * 8 + w;
    const float myq = g_q[(size_t)t * QDIM + lane];
    const float NEGINF = __uint_as_float(0xff800000u);

    // 4 units: (head, side)
#pragma unroll
    for (int u = 0; u < 4; u++) {
        const int h = u >> 1, side = u & 1;
        float qv[HALFD];
#pragma unroll
        for (int c = 0; c < HALFD; c++)
            qv[c] = __shfl_sync(0xffffffffu, myq, h * 16 + side * 8 + c);

        float s[8];  // lane owns keys n = i*32 + lane
#pragma unroll
        for (int i = 0; i < 8; i++) {
            const int n = i * 32 + lane;
            const float4 k0 = *(const float4*)&ks[(u * NKEYS + n) * HALFD];
            const float4 k1 = *(const float4*)&ks[(u * NKEYS + n) * HALFD + 4];
            s[i] = qv[0] * k0.x + qv[1] * k0.y + qv[2] * k0.z + qv[3] * k0.w
                 + qv[4] * k1.x + qv[5] * k1.y + qv[6] * k1.z + qv[7] * k1.w;
        }
#pragma unroll
        for (int r = 0; r < KNN; r++) {
            float bv = NEGINF; int bn = 0x7fffffff;
#pragma unroll
            for (int i = 0; i < 8; i++)
                if (s[i] > bv) { bv = s[i]; bn = i * 32 + lane; }
#pragma unroll
            for (int off = 16; off; off >>= 1) {
                const float ov = __shfl_xor_sync(0xffffffffu, bv, off);
                const int   on = __shfl_xor_sync(0xffffffffu, bn, off);
                if (ov > bv || (ov == bv && on < bn)) { bv = ov; bn = on; }
            }
            if (lane == 0) { sc_s[w][h][side][r] = bv; id_s[w][h][side][r] = bn; }
            if ((bn & 31) == lane) s[bn >> 5] = NEGINF;   // kill winner
        }
    }
    __syncwarp();

    // Combine per head: 64 combos = sc1[a] + sc2[b], flat c = a*8 + b
#pragma unroll
    for (int h = 0; h < 2; h++) {
        float v0 = sc_s[w][h][0][lane >> 3]       + sc_s[w][h][1][lane & 7];
        float v1 = sc_s[w][h][0][(lane >> 3) + 4] + sc_s[w][h][1][lane & 7];
#pragma unroll
        for (int r = 0; r < KNN; r++) {
            float bv = v0; int bc = lane;
            if (v1 > bv) { bv = v1; bc = lane + 32; }
#pragma unroll
            for (int off = 16; off; off >>= 1) {
                const float ov = __shfl_xor_sync(0xffffffffu, bv, off);
                const int   oc = __shfl_xor_sync(0xffffffffu, bc, off);
                if (ov > bv || (ov == bv && oc < bc)) { bv = ov; bc = oc; }
            }
            if (lane == 0) {
                fsc_s[w][h][r] = bv;
                const int a = bc >> 3, b = bc & 7;
                fid_s[w][h][r] = id_s[w][h][0][a] * NKEYS + id_s[w][h][1][b];
            }
            if (bc == lane)      v0 = NEGINF;
            if (bc == lane + 32) v1 = NEGINF;
        }
    }
    __syncwarp();

    // Softmax over 8 per head; lanes 0..15 each handle one (h,k) output
    if (lane < 16) {
        const int h = lane >> 3, kk = lane & 7;
        float m = NEGINF;
#pragma unroll
        for (int i = 0; i < KNN; i++) m = fmaxf(m, fsc_s[w][h][i]);
        float den = 0.f;
#pragma unroll
        for (int i = 0; i < KNN; i++) den += expf(fsc_s[w][h][i] - m);
        const float wt = expf(fsc_s[w][h][kk] - m) / den;
        g_wt[t * 16 + lane] = wt;
        g_id[t * 16 + lane] = fid_s[w][h][kk];
    }
}

// ---------------------------------------------------------------------------
// Kernel 4: out[t] = sum_{k<16} w_k * values[idx_k]  (R9/R13-proven: ~53us)
// ---------------------------------------------------------------------------
__global__ __launch_bounds__(256, 1)
void k4_gather(const float* __restrict__ values, float* __restrict__ out)
{
    __shared__ float ws[16];
    __shared__ int   is[16];
    const int t = blockIdx.x;
    if (threadIdx.x < 16) {
        ws[threadIdx.x] = g_wt[t * 16 + threadIdx.x];
        is[threadIdx.x] = g_id[t * 16 + threadIdx.x];
    }
    __syncthreads();
    const int col = threadIdx.x << 2;
    float4 acc = make_float4(0.f, 0.f, 0.f, 0.f);
#pragma unroll
    for (int k = 0; k < 16; k++) {
        const float4 v = __ldg((const float4*)(values + (size_t)is[k] * D_IN + col));
        const float wk = ws[k];
        acc.x = fmaf(wk, v.x, acc.x);
        acc.y = fmaf(wk, v.y, acc.y);
        acc.z = fmaf(wk, v.z, acc.z);
        acc.w = fmaf(wk, v.w, acc.w);
    }
    *(float4*)(out + (size_t)t * D_IN + col) = acc;
}

// ---------------------------------------------------------------------------
extern "C" void kernel_launch(void* const* d_in, const int* in_sizes, int n_in,
                              void* d_out, int out_size)
{
    const float* x      = (const float*)d_in[0];
    const float* W1     = (const float*)d_in[1];
    const float* b1     = (const float*)d_in[2];
    const float* W2     = (const float*)d_in[3];
    const float* b2     = (const float*)d_in[4];
    const float* keys   = (const float*)d_in[5];
    const float* values = (const float*)d_in[6];
    float* out = (float*)d_out;

    cudaFuncSetAttribute(k1_gemm_relu_q,
                         cudaFuncAttributeMaxDynamicSharedMemorySize, SMEM_BYTES);

    k1_gemm_relu_q<<<T_TOK / BM, 256, SMEM_BYTES>>>(x, W1, b1, W2, b2);
    k3_topk<<<T_TOK / 8, 256>>>(keys);
    k4_gather<<<T_TOK, 256>>>(values, out);
}